// round 8
// baseline (speedup 1.0000x reference)
#include <cuda_runtime.h>
#include <cstdint>

// Problem constants
#define Bn 64
#define Sn 512
#define Nn 128
#define Dn 768
#define On 3

// Scratch (device globals -- no allocations allowed)
__device__ float g_x[(size_t)Bn * Nn * Dn];      // exact node features (residual stream)
__device__ float g_xr[(size_t)Bn * Nn * Dn];     // tf32-rounded, K-permuted copy (MMA input)
__device__ float g_t[(size_t)Bn * Nn * Dn];      // span sums, rounded+permuted [B*N, D]
__device__ float g_tT[(size_t)Bn * Dn * Nn];     // (x@W)^T per batch, rounded+permuted [B][D][N]
__device__ float g_adj[(size_t)Bn * Nn * Nn];    // clamped adjacency, permuted cols (exact 0/1)
__device__ float g_denom[(size_t)Bn * Nn];       // row-degree + 1e-7
__device__ float g_tmax[(size_t)Bn * Dn];        // target max-pool
__device__ float g_Wt[4 * (size_t)Dn * Dn];      // W^T [N,K], rounded + K-permuted

// ===========================================================================
// helpers
// ===========================================================================
__device__ __forceinline__ uint32_t smem_u32(const void* p) {
    uint32_t a;
    asm("{ .reg .u64 t; cvta.to.shared.u64 t, %1; cvt.u32.u64 %0, t; }" : "=r"(a) : "l"(p));
    return a;
}
__device__ __forceinline__ float f2tf(float f) {
    uint32_t u;
    asm("cvt.rna.tf32.f32 %0, %1;" : "=r"(u) : "f"(f));
    return __uint_as_float(u);
}
// K-permutation within each 16-column group (involution)
__device__ __forceinline__ int permc(int c) {
    return (c & ~15) | ((c & 3) << 2) | ((c >> 2) & 3);
}
#define CP_ASYNC16(dst, src) \
    asm volatile("cp.async.cg.shared.global [%0], [%1], 16;" :: "r"(dst), "l"(src) : "memory")
#define CP_COMMIT() asm volatile("cp.async.commit_group;" ::: "memory")
#define CP_WAIT(n)  asm volatile("cp.async.wait_group %0;" :: "n"(n) : "memory")

__device__ __forceinline__ void mma_tf32(float& c0, float& c1, float& c2, float& c3,
                                         float a0, float a1, float a2, float a3,
                                         float b0, float b1) {
    asm volatile(
        "mma.sync.aligned.m16n8k8.row.col.f32.tf32.tf32.f32 "
        "{%0,%1,%2,%3}, {%4,%5,%6,%7}, {%8,%9}, {%0,%1,%2,%3};"
        : "+f"(c0), "+f"(c1), "+f"(c2), "+f"(c3)
        : "r"(__float_as_uint(a0)), "r"(__float_as_uint(a1)),
          "r"(__float_as_uint(a2)), "r"(__float_as_uint(a3)),
          "r"(__float_as_uint(b0)), "r"(__float_as_uint(b1)));
}

// ===========================================================================
// small prep kernels
// ===========================================================================
__global__ void adj_kernel(const float* __restrict__ dg, const float* __restrict__ dg1) {
    int row = blockIdx.x;
    int tid = threadIdx.x;
    float a = dg[(size_t)row * Nn + tid] + dg1[(size_t)row * Nn + tid];
    a = fminf(a, 1.0f);
    g_adj[(size_t)row * Nn + permc(tid)] = a;
    __shared__ float s[128];
    s[tid] = a;
    __syncthreads();
    #pragma unroll
    for (int st = 64; st > 0; st >>= 1) {
        if (tid < st) s[tid] += s[tid + st];
        __syncthreads();
    }
    if (tid == 0) g_denom[row] = s[0] + 1e-7f;
}

__global__ void span_kernel(const float* __restrict__ se, const int* __restrict__ tran) {
    int row = blockIdx.x;
    int b = row >> 7;
    int s0 = tran[row * 2] + 1;
    int e0 = tran[row * 2 + 1] + 1;
    for (int d = threadIdx.x; d < Dn; d += 256) {
        float acc = 0.0f;
        for (int s = s0; s < e0; ++s)
            acc += se[((size_t)b * Sn + s) * Dn + d];
        g_t[(size_t)row * Dn + permc(d)] = f2tf(acc);
    }
}

__global__ void tmax_kernel(const float* __restrict__ se, const int* __restrict__ tspan) {
    int b = blockIdx.x;
    int l = tspan[b * 2];
    int r = tspan[b * 2 + 1];
    for (int d = threadIdx.x; d < Dn; d += 256) {
        float m = -3.402823466e38f;
        for (int s = l; s < r; ++s)
            m = fmaxf(m, se[((size_t)b * Sn + s) * Dn + d]);
        g_tmax[(size_t)b * Dn + d] = m;
    }
}

// transpose + round + K-permute 4 weight matrices [K=768, N=768] -> g_Wt[w][N][Kperm]
__global__ void wtrans_kernel(const float* __restrict__ W0, const float* __restrict__ W1,
                              const float* __restrict__ W2, const float* __restrict__ W3) {
    __shared__ float t[32][33];
    int w = blockIdx.z;
    const float* W = (w == 0) ? W0 : (w == 1) ? W1 : (w == 2) ? W2 : W3;
    float* O = g_Wt + (size_t)w * Dn * Dn;
    int nx = blockIdx.x * 32;
    int ky = blockIdx.y * 32;
    int tx = threadIdx.x;
    for (int i = threadIdx.y; i < 32; i += 8)
        t[i][tx] = W[(size_t)(ky + i) * Dn + nx + tx];
    __syncthreads();
    for (int i = threadIdx.y; i < 32; i += 8)
        O[(size_t)(nx + i) * Dn + permc(ky + tx)] = f2tf(t[tx][i]);
}

// ===========================================================================
// tf32 mma.sync GEMM: C[M,N] = A[M,K] @ B^T  (B as [N,K]; K pre-permuted, tf32)
// 128x128 block tile, BK=16, 128 threads (4 warps of 64x64)
// 4-stage cp.async pipeline in dynamic smem (TSTRIDE=16: conflict-free), 2 CTAs/SM
// MODE 0: g_x = relu(acc) (exact) + g_xr rounded/permuted    (proj)
// MODE 1: C^T per-batch store into g_tT (rounded/permuted)   (h@W)
// MODE 2: g_x += relu(acc/denom + bias); g_xr rounded copy   (adjacency)
// ===========================================================================
#define BK 16
#define TSTRIDE 16
#define TILE_F (128 * TSTRIDE)
#define NST 4
#define GEMM_SMEM_BYTES (2 * NST * TILE_F * 4)   // 65536
#define NTHR 128

template <int MODE, int KTILES>
__global__ void __launch_bounds__(NTHR, 2)
gemm_mma(const float* __restrict__ A, const float* __restrict__ B,
         const float* __restrict__ bias, int lda, int ldb) {
    extern __shared__ float smem[];

    int tid = threadIdx.x;
    int lane = tid & 31;
    int warp = tid >> 5;          // 0..3
    int wm = (warp >> 1) * 64;    // warp row base (0/64)
    int wn = (warp & 1) * 64;     // warp col base (0/64)
    int lg = lane >> 2;           // 0..7
    int tg = lane & 3;            // 0..3

    const float* Ab;
    const float* Bb;
    int aRow0, bRow0;
    if (MODE == 2) {
        Ab = A + (size_t)blockIdx.y * Nn * Nn;     // adj[b]
        Bb = B + (size_t)blockIdx.y * Dn * Nn;     // g_tT[b]
        aRow0 = 0;
        bRow0 = blockIdx.x * 128;
    } else {
        Ab = A;
        Bb = B;
        aRow0 = blockIdx.y * 128;
        bRow0 = blockIdx.x * 128;
    }

    float c[4][8][4];
    #pragma unroll
    for (int i = 0; i < 4; ++i)
        #pragma unroll
        for (int j = 0; j < 8; ++j)
            #pragma unroll
            for (int k = 0; k < 4; ++k) c[i][j][k] = 0.0f;

    uint32_t sAbase[NST], sBbase[NST];
    #pragma unroll
    for (int s = 0; s < NST; ++s) {
        sAbase[s] = smem_u32(smem + 2 * s * TILE_F);
        sBbase[s] = smem_u32(smem + (2 * s + 1) * TILE_F);
    }

    auto load_stage = [&](int it, int buf) {
        int k0 = it * BK;
        #pragma unroll
        for (int i = 0; i < 4; ++i) {
            int id = tid + i * NTHR;     // 0..511
            int row = id >> 2;
            int seg = id & 3;
            CP_ASYNC16(sAbase[buf] + (row * TSTRIDE + seg * 4) * 4,
                       Ab + (size_t)(aRow0 + row) * lda + k0 + seg * 4);
            CP_ASYNC16(sBbase[buf] + (row * TSTRIDE + seg * 4) * 4,
                       Bb + (size_t)(bRow0 + row) * ldb + k0 + seg * 4);
        }
        CP_COMMIT();
    };

    load_stage(0, 0);
    load_stage(1, 1);
    load_stage(2, 2);
    for (int it = 0; it < KTILES; ++it) {
        int buf = it & (NST - 1);
        if (it == KTILES - 1) { CP_WAIT(0); } else { CP_WAIT(2); }
        __syncthreads();
        if (it + 3 < KTILES) load_stage(it + 3, (it + 3) & (NST - 1));

        const float* as = smem + 2 * buf * TILE_F;
        const float* bs = smem + (2 * buf + 1) * TILE_F;
        // physical cols [4tg..4tg+3] hold logical k = {tg, tg+4, tg+8, tg+12}
        float4 av[4][2], bv[8];
        #pragma unroll
        for (int mi = 0; mi < 4; ++mi) {
            av[mi][0] = *(const float4*)&as[(wm + mi * 16 + lg) * TSTRIDE + 4 * tg];
            av[mi][1] = *(const float4*)&as[(wm + mi * 16 + lg + 8) * TSTRIDE + 4 * tg];
        }
        #pragma unroll
        for (int ni = 0; ni < 8; ++ni)
            bv[ni] = *(const float4*)&bs[(wn + ni * 8 + lg) * TSTRIDE + 4 * tg];
        #pragma unroll
        for (int mi = 0; mi < 4; ++mi)
            #pragma unroll
            for (int ni = 0; ni < 8; ++ni) {
                mma_tf32(c[mi][ni][0], c[mi][ni][1], c[mi][ni][2], c[mi][ni][3],
                         av[mi][0].x, av[mi][1].x, av[mi][0].y, av[mi][1].y,
                         bv[ni].x, bv[ni].y);
                mma_tf32(c[mi][ni][0], c[mi][ni][1], c[mi][ni][2], c[mi][ni][3],
                         av[mi][0].z, av[mi][1].z, av[mi][0].w, av[mi][1].w,
                         bv[ni].z, bv[ni].w);
            }
    }
    __syncthreads();

    // ---- epilogue ----
    if (MODE == 0) {
        size_t row0 = (size_t)blockIdx.y * 128;
        #pragma unroll
        for (int mi = 0; mi < 4; ++mi) {
            int r = wm + mi * 16 + lg;
            #pragma unroll
            for (int ni = 0; ni < 8; ++ni) {
                int cc = blockIdx.x * 128 + wn + ni * 8 + 2 * tg;
                float v0 = fmaxf(c[mi][ni][0], 0.0f);
                float v1 = fmaxf(c[mi][ni][1], 0.0f);
                float v2 = fmaxf(c[mi][ni][2], 0.0f);
                float v3 = fmaxf(c[mi][ni][3], 0.0f);
                g_x[(row0 + r) * Dn + cc]          = v0;
                g_x[(row0 + r) * Dn + cc + 1]      = v1;
                g_x[(row0 + r + 8) * Dn + cc]      = v2;
                g_x[(row0 + r + 8) * Dn + cc + 1]  = v3;
                g_xr[(row0 + r) * Dn + permc(cc)]         = f2tf(v0);
                g_xr[(row0 + r) * Dn + permc(cc + 1)]     = f2tf(v1);
                g_xr[(row0 + r + 8) * Dn + permc(cc)]     = f2tf(v2);
                g_xr[(row0 + r + 8) * Dn + permc(cc + 1)] = f2tf(v3);
            }
        }
    } else if (MODE == 1) {
        int b = blockIdx.y;
        float* outb = g_tT + ((size_t)b * Dn + blockIdx.x * 128) * Nn;
        #pragma unroll
        for (int half = 0; half < 2; ++half) {
            __syncthreads();
            // warps with wn == half*64 deposit their fragments: sc[c_local][r]
            if ((wn >> 6) == half) {
                #pragma unroll
                for (int mi = 0; mi < 4; ++mi) {
                    int r = wm + mi * 16 + lg;
                    #pragma unroll
                    for (int ni = 0; ni < 8; ++ni) {
                        int cl = ni * 8 + 2 * tg;
                        smem[cl * 132 + r]           = c[mi][ni][0];
                        smem[(cl + 1) * 132 + r]     = c[mi][ni][1];
                        smem[cl * 132 + r + 8]       = c[mi][ni][2];
                        smem[(cl + 1) * 132 + r + 8] = c[mi][ni][3];
                    }
                }
            }
            __syncthreads();
            // write 64 tT rows (each 128 floats) coalesced; permute K(=node) cols
            for (int i = tid; i < 64 * 32; i += NTHR) {
                int row = i >> 5;
                int seg = i & 31;
                float4 v;
                v.x = f2tf(smem[row * 132 + permc(seg * 4 + 0)]);
                v.y = f2tf(smem[row * 132 + permc(seg * 4 + 1)]);
                v.z = f2tf(smem[row * 132 + permc(seg * 4 + 2)]);
                v.w = f2tf(smem[row * 132 + permc(seg * 4 + 3)]);
                *(float4*)&outb[(size_t)(half * 64 + row) * Nn + seg * 4] = v;
            }
        }
    } else {
        int b = blockIdx.y;
        #pragma unroll
        for (int mi = 0; mi < 4; ++mi) {
            int r = wm + mi * 16 + lg;
            float id0 = 1.0f / g_denom[b * Nn + r];
            float id1 = 1.0f / g_denom[b * Nn + r + 8];
            size_t row0 = (size_t)(b * Nn + r);
            size_t row1 = row0 + 8;
            #pragma unroll
            for (int ni = 0; ni < 8; ++ni) {
                int cc = blockIdx.x * 128 + wn + ni * 8 + 2 * tg;
                float n0 = g_x[row0 * Dn + cc]     + fmaxf(c[mi][ni][0] * id0 + bias[cc], 0.0f);
                float n1 = g_x[row0 * Dn + cc + 1] + fmaxf(c[mi][ni][1] * id0 + bias[cc + 1], 0.0f);
                float n2 = g_x[row1 * Dn + cc]     + fmaxf(c[mi][ni][2] * id1 + bias[cc], 0.0f);
                float n3 = g_x[row1 * Dn + cc + 1] + fmaxf(c[mi][ni][3] * id1 + bias[cc + 1], 0.0f);
                g_x[row0 * Dn + cc]     = n0;
                g_x[row0 * Dn + cc + 1] = n1;
                g_x[row1 * Dn + cc]     = n2;
                g_x[row1 * Dn + cc + 1] = n3;
                g_xr[row0 * Dn + permc(cc)]     = f2tf(n0);
                g_xr[row0 * Dn + permc(cc + 1)] = f2tf(n1);
                g_xr[row1 * Dn + permc(cc)]     = f2tf(n2);
                g_xr[row1 * Dn + permc(cc + 1)] = f2tf(n3);
            }
        }
    }
}

// ===========================================================================
// head: gcn_target (node-span sum) + concat + fc + tanh
// ===========================================================================
__global__ void head_kernel(const float* __restrict__ fcW, const float* __restrict__ fcb,
                            const int* __restrict__ gspan, float* __restrict__ out) {
    int b = blockIdx.x;
    int tid = threadIdx.x;
    int gs = gspan[b * 2];
    int ge = gspan[b * 2 + 1];
    float p0 = 0.0f, p1 = 0.0f, p2 = 0.0f;
    for (int d = tid; d < Dn; d += 256) {
        float tm = g_tmax[(size_t)b * Dn + d];
        float gt = 0.0f;
        for (int n = gs; n < ge; ++n)
            gt += g_x[((size_t)b * Nn + n) * Dn + d];
        p0 += tm * fcW[d * On + 0] + gt * fcW[(Dn + d) * On + 0];
        p1 += tm * fcW[d * On + 1] + gt * fcW[(Dn + d) * On + 1];
        p2 += tm * fcW[d * On + 2] + gt * fcW[(Dn + d) * On + 2];
    }
    __shared__ float r0[256], r1[256], r2[256];
    r0[tid] = p0; r1[tid] = p1; r2[tid] = p2;
    __syncthreads();
    #pragma unroll
    for (int st = 128; st > 0; st >>= 1) {
        if (tid < st) { r0[tid] += r0[tid + st]; r1[tid] += r1[tid + st]; r2[tid] += r2[tid + st]; }
        __syncthreads();
    }
    if (tid == 0) {
        out[b * On + 0] = tanhf(r0[0] + fcb[0]);
        out[b * On + 1] = tanhf(r1[0] + fcb[1]);
        out[b * On + 2] = tanhf(r2[0] + fcb[2]);
    }
}

// ===========================================================================
extern "C" void kernel_launch(void* const* d_in, const int* in_sizes, int n_in,
                              void* d_out, int out_size) {
    const float* se    = (const float*)d_in[0];
    const float* dg    = (const float*)d_in[1];
    const float* dg1   = (const float*)d_in[2];
    const float* Wproj = (const float*)d_in[3];
    const float* Wg1   = (const float*)d_in[4];
    const float* bg1   = (const float*)d_in[5];
    const float* Wg2   = (const float*)d_in[6];
    const float* bg2   = (const float*)d_in[7];
    const float* Wg3   = (const float*)d_in[8];
    const float* bg3   = (const float*)d_in[9];
    const float* fcW   = (const float*)d_in[10];
    const float* fcb   = (const float*)d_in[11];
    const int*   tspan = (const int*)d_in[12];
    const int*   tran  = (const int*)d_in[13];
    const int*   gspan = (const int*)d_in[14];
    float* out = (float*)d_out;

    float *pt, *pxr, *ptT, *padj, *pWt;
    cudaGetSymbolAddress((void**)&pt, g_t);
    cudaGetSymbolAddress((void**)&pxr, g_xr);
    cudaGetSymbolAddress((void**)&ptT, g_tT);
    cudaGetSymbolAddress((void**)&padj, g_adj);
    cudaGetSymbolAddress((void**)&pWt, g_Wt);

    cudaFuncSetAttribute(gemm_mma<0, 48>, cudaFuncAttributeMaxDynamicSharedMemorySize, GEMM_SMEM_BYTES);
    cudaFuncSetAttribute(gemm_mma<1, 48>, cudaFuncAttributeMaxDynamicSharedMemorySize, GEMM_SMEM_BYTES);
    cudaFuncSetAttribute(gemm_mma<2, 8>,  cudaFuncAttributeMaxDynamicSharedMemorySize, GEMM_SMEM_BYTES);

    dim3 gg(6, 64);

    adj_kernel<<<Bn * Nn, 128>>>(dg, dg1);
    span_kernel<<<Bn * Nn, 256>>>(se, tran);
    tmax_kernel<<<Bn, 256>>>(se, tspan);
    wtrans_kernel<<<dim3(24, 24, 4), dim3(32, 8)>>>(Wproj, Wg1, Wg2, Wg3);

    const size_t WSZ = (size_t)Dn * Dn;

    // x = relu(tmps @ W_proj)
    gemm_mma<0, 48><<<gg, NTHR, GEMM_SMEM_BYTES>>>(pt, pWt + 0 * WSZ, nullptr, Dn, Dn);

    // 3 GCN layers: tT = (x @ Wg)^T ; x += relu(adj @ t / denom + b)
    gemm_mma<1, 48><<<gg, NTHR, GEMM_SMEM_BYTES>>>(pxr, pWt + 1 * WSZ, nullptr, Dn, Dn);
    gemm_mma<2, 8><<<gg, NTHR, GEMM_SMEM_BYTES>>>(padj, ptT, bg1, Nn, Nn);
    gemm_mma<1, 48><<<gg, NTHR, GEMM_SMEM_BYTES>>>(pxr, pWt + 2 * WSZ, nullptr, Dn, Dn);
    gemm_mma<2, 8><<<gg, NTHR, GEMM_SMEM_BYTES>>>(padj, ptT, bg2, Nn, Nn);
    gemm_mma<1, 48><<<gg, NTHR, GEMM_SMEM_BYTES>>>(pxr, pWt + 3 * WSZ, nullptr, Dn, Dn);
    gemm_mma<2, 8><<<gg, NTHR, GEMM_SMEM_BYTES>>>(padj, ptT, bg3, Nn, Nn);

    head_kernel<<<Bn, 256>>>(fcW, fcb, gspan, out);
}

// round 9
// speedup vs baseline: 1.1432x; 1.1432x over previous
#include <cuda_runtime.h>
#include <cstdint>

// Problem constants
#define Bn 64
#define Sn 512
#define Nn 128
#define Dn 768
#define On 3

// Scratch (device globals -- no allocations allowed)
__device__ float g_x[(size_t)Bn * Nn * Dn];      // exact node features (residual stream)
__device__ float g_xr[(size_t)Bn * Nn * Dn];     // tf32-rounded, K-permuted copy (MMA input)
__device__ float g_t[(size_t)Bn * Nn * Dn];      // span sums, rounded+permuted [B*N, D]
__device__ float g_tT[(size_t)Bn * Dn * Nn];     // (x@W)^T per batch, rounded+permuted [B][D][N]
__device__ float g_adj[(size_t)Bn * Nn * Nn];    // clamped adjacency, permuted cols (exact 0/1)
__device__ float g_denom[(size_t)Bn * Nn];       // row-degree + 1e-7
__device__ float g_tmax[(size_t)Bn * Dn];        // target max-pool
__device__ float g_Wt[4 * (size_t)Dn * Dn];      // W^T [N,K], rounded + K-permuted

// ===========================================================================
// helpers
// ===========================================================================
__device__ __forceinline__ uint32_t smem_u32(const void* p) {
    uint32_t a;
    asm("{ .reg .u64 t; cvta.to.shared.u64 t, %1; cvt.u32.u64 %0, t; }" : "=r"(a) : "l"(p));
    return a;
}
__device__ __forceinline__ float f2tf(float f) {
    uint32_t u;
    asm("cvt.rna.tf32.f32 %0, %1;" : "=r"(u) : "f"(f));
    return __uint_as_float(u);
}
// K-permutation within each 16-column group (involution)
__device__ __forceinline__ int permc(int c) {
    return (c & ~15) | ((c & 3) << 2) | ((c >> 2) & 3);
}
#define CP_ASYNC16(dst, src) \
    asm volatile("cp.async.cg.shared.global [%0], [%1], 16;" :: "r"(dst), "l"(src) : "memory")
#define CP_COMMIT() asm volatile("cp.async.commit_group;" ::: "memory")
#define CP_WAIT(n)  asm volatile("cp.async.wait_group %0;" :: "n"(n) : "memory")

__device__ __forceinline__ void mma_tf32(float& c0, float& c1, float& c2, float& c3,
                                         float a0, float a1, float a2, float a3,
                                         float b0, float b1) {
    asm volatile(
        "mma.sync.aligned.m16n8k8.row.col.f32.tf32.tf32.f32 "
        "{%0,%1,%2,%3}, {%4,%5,%6,%7}, {%8,%9}, {%0,%1,%2,%3};"
        : "+f"(c0), "+f"(c1), "+f"(c2), "+f"(c3)
        : "r"(__float_as_uint(a0)), "r"(__float_as_uint(a1)),
          "r"(__float_as_uint(a2)), "r"(__float_as_uint(a3)),
          "r"(__float_as_uint(b0)), "r"(__float_as_uint(b1)));
}

// ===========================================================================
// small prep kernels
// ===========================================================================
__global__ void adj_kernel(const float* __restrict__ dg, const float* __restrict__ dg1) {
    int row = blockIdx.x;
    int tid = threadIdx.x;
    float a = dg[(size_t)row * Nn + tid] + dg1[(size_t)row * Nn + tid];
    a = fminf(a, 1.0f);
    g_adj[(size_t)row * Nn + permc(tid)] = a;
    __shared__ float s[128];
    s[tid] = a;
    __syncthreads();
    #pragma unroll
    for (int st = 64; st > 0; st >>= 1) {
        if (tid < st) s[tid] += s[tid + st];
        __syncthreads();
    }
    if (tid == 0) g_denom[row] = s[0] + 1e-7f;
}

__global__ void span_kernel(const float* __restrict__ se, const int* __restrict__ tran) {
    int row = blockIdx.x;
    int b = row >> 7;
    int s0 = tran[row * 2] + 1;
    int e0 = tran[row * 2 + 1] + 1;
    for (int d = threadIdx.x; d < Dn; d += 256) {
        float acc = 0.0f;
        for (int s = s0; s < e0; ++s)
            acc += se[((size_t)b * Sn + s) * Dn + d];
        g_t[(size_t)row * Dn + permc(d)] = f2tf(acc);
    }
}

__global__ void tmax_kernel(const float* __restrict__ se, const int* __restrict__ tspan) {
    int b = blockIdx.x;
    int l = tspan[b * 2];
    int r = tspan[b * 2 + 1];
    for (int d = threadIdx.x; d < Dn; d += 256) {
        float m = -3.402823466e38f;
        for (int s = l; s < r; ++s)
            m = fmaxf(m, se[((size_t)b * Sn + s) * Dn + d]);
        g_tmax[(size_t)b * Dn + d] = m;
    }
}

// transpose + round + K-permute 4 weight matrices [K=768, N=768] -> g_Wt[w][N][Kperm]
__global__ void wtrans_kernel(const float* __restrict__ W0, const float* __restrict__ W1,
                              const float* __restrict__ W2, const float* __restrict__ W3) {
    __shared__ float t[32][33];
    int w = blockIdx.z;
    const float* W = (w == 0) ? W0 : (w == 1) ? W1 : (w == 2) ? W2 : W3;
    float* O = g_Wt + (size_t)w * Dn * Dn;
    int nx = blockIdx.x * 32;
    int ky = blockIdx.y * 32;
    int tx = threadIdx.x;
    for (int i = threadIdx.y; i < 32; i += 8)
        t[i][tx] = W[(size_t)(ky + i) * Dn + nx + tx];
    __syncthreads();
    for (int i = threadIdx.y; i < 32; i += 8)
        O[(size_t)(nx + i) * Dn + permc(ky + tx)] = f2tf(t[tx][i]);
}

// ===========================================================================
// tf32 mma.sync GEMM: C[M,N] = A[M,K] @ B^T  (B as [N,K]; K pre-permuted, tf32)
// 128x128 block tile, BK=16, 256 threads (8 warps of 64x32)
// 6-stage cp.async pipeline, ONE sync per TWO k-tiles, 2 CTAs/SM
// MODE 0: g_x = relu(acc) (exact) + g_xr rounded/permuted    (proj)
// MODE 1: C^T per-batch store into g_tT (rounded/permuted)   (h@W)
// MODE 2: g_x += relu(acc/denom + bias); g_xr copy if WXR    (adjacency)
// ===========================================================================
#define BK 16
#define TSTRIDE 16
#define TILE_F (128 * TSTRIDE)
#define NST 6
#define GEMM_SMEM_BYTES (2 * NST * TILE_F * 4)   // 98304

template <int MODE, int KTILES, int WXR>
__global__ void __launch_bounds__(256, 2)
gemm_mma(const float* __restrict__ A, const float* __restrict__ B,
         const float* __restrict__ bias, int lda, int ldb) {
    extern __shared__ float smem[];

    int tid = threadIdx.x;
    int lane = tid & 31;
    int warp = tid >> 5;
    int wm = (warp >> 2) * 64;    // warp row base (0/64)
    int wn = (warp & 3) * 32;     // warp col base (0..96)
    int lg = lane >> 2;           // 0..7
    int tg = lane & 3;            // 0..3

    const float* Ab;
    const float* Bb;
    int aRow0, bRow0;
    if (MODE == 2) {
        Ab = A + (size_t)blockIdx.y * Nn * Nn;     // adj[b]
        Bb = B + (size_t)blockIdx.y * Dn * Nn;     // g_tT[b]
        aRow0 = 0;
        bRow0 = blockIdx.x * 128;
    } else {
        Ab = A;
        Bb = B;
        aRow0 = blockIdx.y * 128;
        bRow0 = blockIdx.x * 128;
    }

    float c[4][4][4];
    #pragma unroll
    for (int i = 0; i < 4; ++i)
        #pragma unroll
        for (int j = 0; j < 4; ++j)
            #pragma unroll
            for (int k = 0; k < 4; ++k) c[i][j][k] = 0.0f;

    uint32_t sAbase[NST], sBbase[NST];
    #pragma unroll
    for (int s = 0; s < NST; ++s) {
        sAbase[s] = smem_u32(smem + 2 * s * TILE_F);
        sBbase[s] = smem_u32(smem + (2 * s + 1) * TILE_F);
    }

    auto load_stage = [&](int it, int buf) {
        int k0 = it * BK;
        #pragma unroll
        for (int i = 0; i < 2; ++i) {
            int id = tid + i * 256;
            int row = id >> 2;
            int seg = id & 3;
            CP_ASYNC16(sAbase[buf] + (row * TSTRIDE + seg * 4) * 4,
                       Ab + (size_t)(aRow0 + row) * lda + k0 + seg * 4);
            CP_ASYNC16(sBbase[buf] + (row * TSTRIDE + seg * 4) * 4,
                       Bb + (size_t)(bRow0 + row) * ldb + k0 + seg * 4);
        }
        CP_COMMIT();
    };

    // prologue: pairs 0 and 1 (stages 0..3)
    load_stage(0, 0);
    load_stage(1, 1);
    load_stage(2, 2);
    load_stage(3, 3);

    const int P = KTILES / 2;
    for (int p = 0; p < P; ++p) {
        if (p == P - 1) { CP_WAIT(0); } else { CP_WAIT(2); }
        __syncthreads();
        if (p + 2 < P) {
            load_stage(2 * (p + 2),     (2 * p + 4) % 6);
            load_stage(2 * (p + 2) + 1, (2 * p + 5) % 6);
        }
        int s0 = (2 * p) % 6;
        #pragma unroll 1
        for (int ss = 0; ss < 2; ++ss) {
            const float* as = smem + 2 * (s0 + ss) * TILE_F;
            const float* bs = smem + (2 * (s0 + ss) + 1) * TILE_F;
            // physical cols [4tg..4tg+3] hold logical k = {tg, tg+4, tg+8, tg+12}
            float4 av[4][2], bv[4];
            #pragma unroll
            for (int mi = 0; mi < 4; ++mi) {
                av[mi][0] = *(const float4*)&as[(wm + mi * 16 + lg) * TSTRIDE + 4 * tg];
                av[mi][1] = *(const float4*)&as[(wm + mi * 16 + lg + 8) * TSTRIDE + 4 * tg];
            }
            #pragma unroll
            for (int ni = 0; ni < 4; ++ni)
                bv[ni] = *(const float4*)&bs[(wn + ni * 8 + lg) * TSTRIDE + 4 * tg];
            #pragma unroll
            for (int mi = 0; mi < 4; ++mi)
                #pragma unroll
                for (int ni = 0; ni < 4; ++ni) {
                    mma_tf32(c[mi][ni][0], c[mi][ni][1], c[mi][ni][2], c[mi][ni][3],
                             av[mi][0].x, av[mi][1].x, av[mi][0].y, av[mi][1].y,
                             bv[ni].x, bv[ni].y);
                    mma_tf32(c[mi][ni][0], c[mi][ni][1], c[mi][ni][2], c[mi][ni][3],
                             av[mi][0].z, av[mi][1].z, av[mi][0].w, av[mi][1].w,
                             bv[ni].z, bv[ni].w);
                }
        }
    }
    __syncthreads();

    // ---- epilogue ----
    if (MODE == 0) {
        size_t row0 = (size_t)blockIdx.y * 128;
        #pragma unroll
        for (int mi = 0; mi < 4; ++mi) {
            int r = wm + mi * 16 + lg;
            #pragma unroll
            for (int ni = 0; ni < 4; ++ni) {
                int cc = blockIdx.x * 128 + wn + ni * 8 + 2 * tg;
                float v0 = fmaxf(c[mi][ni][0], 0.0f);
                float v1 = fmaxf(c[mi][ni][1], 0.0f);
                float v2 = fmaxf(c[mi][ni][2], 0.0f);
                float v3 = fmaxf(c[mi][ni][3], 0.0f);
                g_x[(row0 + r) * Dn + cc]          = v0;
                g_x[(row0 + r) * Dn + cc + 1]      = v1;
                g_x[(row0 + r + 8) * Dn + cc]      = v2;
                g_x[(row0 + r + 8) * Dn + cc + 1]  = v3;
                g_xr[(row0 + r) * Dn + permc(cc)]         = f2tf(v0);
                g_xr[(row0 + r) * Dn + permc(cc + 1)]     = f2tf(v1);
                g_xr[(row0 + r + 8) * Dn + permc(cc)]     = f2tf(v2);
                g_xr[(row0 + r + 8) * Dn + permc(cc + 1)] = f2tf(v3);
            }
        }
    } else if (MODE == 1) {
        int b = blockIdx.y;
        float* outb = g_tT + ((size_t)b * Dn + blockIdx.x * 128) * Nn;
        #pragma unroll
        for (int half = 0; half < 2; ++half) {
            __syncthreads();
            if ((wn >> 6) == half) {
                #pragma unroll
                for (int mi = 0; mi < 4; ++mi) {
                    int r = wm + mi * 16 + lg;
                    #pragma unroll
                    for (int ni = 0; ni < 4; ++ni) {
                        int cl = (wn & 63) + ni * 8 + 2 * tg;
                        smem[cl * 132 + r]           = c[mi][ni][0];
                        smem[(cl + 1) * 132 + r]     = c[mi][ni][1];
                        smem[cl * 132 + r + 8]       = c[mi][ni][2];
                        smem[(cl + 1) * 132 + r + 8] = c[mi][ni][3];
                    }
                }
            }
            __syncthreads();
            // write 64 tT rows (each 128 floats) coalesced; permute K(=node) cols
            for (int i = tid; i < 64 * 32; i += 256) {
                int row = i >> 5;
                int seg = i & 31;
                float4 v;
                v.x = f2tf(smem[row * 132 + permc(seg * 4 + 0)]);
                v.y = f2tf(smem[row * 132 + permc(seg * 4 + 1)]);
                v.z = f2tf(smem[row * 132 + permc(seg * 4 + 2)]);
                v.w = f2tf(smem[row * 132 + permc(seg * 4 + 3)]);
                *(float4*)&outb[(size_t)(half * 64 + row) * Nn + seg * 4] = v;
            }
        }
    } else {
        int b = blockIdx.y;
        #pragma unroll
        for (int mi = 0; mi < 4; ++mi) {
            int r = wm + mi * 16 + lg;
            float id0 = 1.0f / g_denom[b * Nn + r];
            float id1 = 1.0f / g_denom[b * Nn + r + 8];
            size_t row0 = (size_t)(b * Nn + r);
            size_t row1 = row0 + 8;
            #pragma unroll
            for (int ni = 0; ni < 4; ++ni) {
                int cc = blockIdx.x * 128 + wn + ni * 8 + 2 * tg;
                float n0 = g_x[row0 * Dn + cc]     + fmaxf(c[mi][ni][0] * id0 + bias[cc], 0.0f);
                float n1 = g_x[row0 * Dn + cc + 1] + fmaxf(c[mi][ni][1] * id0 + bias[cc + 1], 0.0f);
                float n2 = g_x[row1 * Dn + cc]     + fmaxf(c[mi][ni][2] * id1 + bias[cc], 0.0f);
                float n3 = g_x[row1 * Dn + cc + 1] + fmaxf(c[mi][ni][3] * id1 + bias[cc + 1], 0.0f);
                g_x[row0 * Dn + cc]     = n0;
                g_x[row0 * Dn + cc + 1] = n1;
                g_x[row1 * Dn + cc]     = n2;
                g_x[row1 * Dn + cc + 1] = n3;
                if (WXR) {
                    g_xr[row0 * Dn + permc(cc)]     = f2tf(n0);
                    g_xr[row0 * Dn + permc(cc + 1)] = f2tf(n1);
                    g_xr[row1 * Dn + permc(cc)]     = f2tf(n2);
                    g_xr[row1 * Dn + permc(cc + 1)] = f2tf(n3);
                }
            }
        }
    }
}

// ===========================================================================
// head: gcn_target (node-span sum) + concat + fc + tanh
// ===========================================================================
__global__ void head_kernel(const float* __restrict__ fcW, const float* __restrict__ fcb,
                            const int* __restrict__ gspan, float* __restrict__ out) {
    int b = blockIdx.x;
    int tid = threadIdx.x;
    int gs = gspan[b * 2];
    int ge = gspan[b * 2 + 1];
    float p0 = 0.0f, p1 = 0.0f, p2 = 0.0f;
    for (int d = tid; d < Dn; d += 256) {
        float tm = g_tmax[(size_t)b * Dn + d];
        float gt = 0.0f;
        for (int n = gs; n < ge; ++n)
            gt += g_x[((size_t)b * Nn + n) * Dn + d];
        p0 += tm * fcW[d * On + 0] + gt * fcW[(Dn + d) * On + 0];
        p1 += tm * fcW[d * On + 1] + gt * fcW[(Dn + d) * On + 1];
        p2 += tm * fcW[d * On + 2] + gt * fcW[(Dn + d) * On + 2];
    }
    __shared__ float r0[256], r1[256], r2[256];
    r0[tid] = p0; r1[tid] = p1; r2[tid] = p2;
    __syncthreads();
    #pragma unroll
    for (int st = 128; st > 0; st >>= 1) {
        if (tid < st) { r0[tid] += r0[tid + st]; r1[tid] += r1[tid + st]; r2[tid] += r2[tid + st]; }
        __syncthreads();
    }
    if (tid == 0) {
        out[b * On + 0] = tanhf(r0[0] + fcb[0]);
        out[b * On + 1] = tanhf(r1[0] + fcb[1]);
        out[b * On + 2] = tanhf(r2[0] + fcb[2]);
    }
}

// ===========================================================================
extern "C" void kernel_launch(void* const* d_in, const int* in_sizes, int n_in,
                              void* d_out, int out_size) {
    const float* se    = (const float*)d_in[0];
    const float* dg    = (const float*)d_in[1];
    const float* dg1   = (const float*)d_in[2];
    const float* Wproj = (const float*)d_in[3];
    const float* Wg1   = (const float*)d_in[4];
    const float* bg1   = (const float*)d_in[5];
    const float* Wg2   = (const float*)d_in[6];
    const float* bg2   = (const float*)d_in[7];
    const float* Wg3   = (const float*)d_in[8];
    const float* bg3   = (const float*)d_in[9];
    const float* fcW   = (const float*)d_in[10];
    const float* fcb   = (const float*)d_in[11];
    const int*   tspan = (const int*)d_in[12];
    const int*   tran  = (const int*)d_in[13];
    const int*   gspan = (const int*)d_in[14];
    float* out = (float*)d_out;

    float *pt, *pxr, *ptT, *padj, *pWt;
    cudaGetSymbolAddress((void**)&pt, g_t);
    cudaGetSymbolAddress((void**)&pxr, g_xr);
    cudaGetSymbolAddress((void**)&ptT, g_tT);
    cudaGetSymbolAddress((void**)&padj, g_adj);
    cudaGetSymbolAddress((void**)&pWt, g_Wt);

    cudaFuncSetAttribute(gemm_mma<0, 48, 1>, cudaFuncAttributeMaxDynamicSharedMemorySize, GEMM_SMEM_BYTES);
    cudaFuncSetAttribute(gemm_mma<1, 48, 0>, cudaFuncAttributeMaxDynamicSharedMemorySize, GEMM_SMEM_BYTES);
    cudaFuncSetAttribute(gemm_mma<2, 8, 1>,  cudaFuncAttributeMaxDynamicSharedMemorySize, GEMM_SMEM_BYTES);
    cudaFuncSetAttribute(gemm_mma<2, 8, 0>,  cudaFuncAttributeMaxDynamicSharedMemorySize, GEMM_SMEM_BYTES);

    dim3 gg(6, 64);

    adj_kernel<<<Bn * Nn, 128>>>(dg, dg1);
    span_kernel<<<Bn * Nn, 256>>>(se, tran);
    tmax_kernel<<<Bn, 256>>>(se, tspan);
    wtrans_kernel<<<dim3(24, 24, 4), dim3(32, 8)>>>(Wproj, Wg1, Wg2, Wg3);

    const size_t WSZ = (size_t)Dn * Dn;

    // x = relu(tmps @ W_proj)
    gemm_mma<0, 48, 1><<<gg, 256, GEMM_SMEM_BYTES>>>(pt, pWt + 0 * WSZ, nullptr, Dn, Dn);

    // 3 GCN layers: tT = (x @ Wg)^T ; x += relu(adj @ t / denom + b)
    gemm_mma<1, 48, 0><<<gg, 256, GEMM_SMEM_BYTES>>>(pxr, pWt + 1 * WSZ, nullptr, Dn, Dn);
    gemm_mma<2, 8, 1><<<gg, 256, GEMM_SMEM_BYTES>>>(padj, ptT, bg1, Nn, Nn);
    gemm_mma<1, 48, 0><<<gg, 256, GEMM_SMEM_BYTES>>>(pxr, pWt + 2 * WSZ, nullptr, Dn, Dn);
    gemm_mma<2, 8, 1><<<gg, 256, GEMM_SMEM_BYTES>>>(padj, ptT, bg2, Nn, Nn);
    gemm_mma<1, 48, 0><<<gg, 256, GEMM_SMEM_BYTES>>>(pxr, pWt + 3 * WSZ, nullptr, Dn, Dn);
    gemm_mma<2, 8, 0><<<gg, 256, GEMM_SMEM_BYTES>>>(padj, ptT, bg3, Nn, Nn);

    head_kernel<<<Bn, 256>>>(fcW, fcb, gspan, out);
}

// round 10
// speedup vs baseline: 1.1829x; 1.0347x over previous
#include <cuda_runtime.h>
#include <cstdint>

// Problem constants
#define Bn 64
#define Sn 512
#define Nn 128
#define Dn 768
#define On 3

// Scratch (device globals -- no allocations allowed)
__device__ float g_x[(size_t)Bn * Nn * Dn];      // exact node features (residual stream)
__device__ float g_xr[(size_t)Bn * Nn * Dn];     // tf32-rounded, K-permuted copy (MMA input)
__device__ float g_t[(size_t)Bn * Nn * Dn];      // span sums, rounded+permuted [B*N, D]
__device__ float g_tT[(size_t)Bn * Dn * Nn];     // (x@W)^T per batch, rounded+permuted [B][D][N]
__device__ float g_adj[(size_t)Bn * Nn * Nn];    // clamped adjacency, permuted cols (exact 0/1)
__device__ float g_denom[(size_t)Bn * Nn];       // row-degree + 1e-7
__device__ float g_tmax[(size_t)Bn * Dn];        // target max-pool
__device__ float g_Wt[4 * (size_t)Dn * Dn];      // W^T [N,K], rounded + K-permuted

// ===========================================================================
// helpers
// ===========================================================================
__device__ __forceinline__ uint32_t smem_u32(const void* p) {
    uint32_t a;
    asm("{ .reg .u64 t; cvta.to.shared.u64 t, %1; cvt.u32.u64 %0, t; }" : "=r"(a) : "l"(p));
    return a;
}
__device__ __forceinline__ float f2tf(float f) {
    uint32_t u;
    asm("cvt.rna.tf32.f32 %0, %1;" : "=r"(u) : "f"(f));
    return __uint_as_float(u);
}
// K-permutation within each 16-column group (involution)
__device__ __forceinline__ int permc(int c) {
    return (c & ~15) | ((c & 3) << 2) | ((c >> 2) & 3);
}
#define CP_ASYNC16(dst, src) \
    asm volatile("cp.async.cg.shared.global [%0], [%1], 16;" :: "r"(dst), "l"(src) : "memory")
#define CP_COMMIT() asm volatile("cp.async.commit_group;" ::: "memory")
#define CP_WAIT(n)  asm volatile("cp.async.wait_group %0;" :: "n"(n) : "memory")

__device__ __forceinline__ void mma_tf32(float& c0, float& c1, float& c2, float& c3,
                                         float a0, float a1, float a2, float a3,
                                         float b0, float b1) {
    asm volatile(
        "mma.sync.aligned.m16n8k8.row.col.f32.tf32.tf32.f32 "
        "{%0,%1,%2,%3}, {%4,%5,%6,%7}, {%8,%9}, {%0,%1,%2,%3};"
        : "+f"(c0), "+f"(c1), "+f"(c2), "+f"(c3)
        : "r"(__float_as_uint(a0)), "r"(__float_as_uint(a1)),
          "r"(__float_as_uint(a2)), "r"(__float_as_uint(a3)),
          "r"(__float_as_uint(b0)), "r"(__float_as_uint(b1)));
}

// ===========================================================================
// small prep kernels
// ===========================================================================
__global__ void adj_kernel(const float* __restrict__ dg, const float* __restrict__ dg1) {
    int row = blockIdx.x;
    int tid = threadIdx.x;
    float a = dg[(size_t)row * Nn + tid] + dg1[(size_t)row * Nn + tid];
    a = fminf(a, 1.0f);
    g_adj[(size_t)row * Nn + permc(tid)] = a;
    __shared__ float s[128];
    s[tid] = a;
    __syncthreads();
    #pragma unroll
    for (int st = 64; st > 0; st >>= 1) {
        if (tid < st) s[tid] += s[tid + st];
        __syncthreads();
    }
    if (tid == 0) g_denom[row] = s[0] + 1e-7f;
}

__global__ void span_kernel(const float* __restrict__ se, const int* __restrict__ tran) {
    int row = blockIdx.x;
    int b = row >> 7;
    int s0 = tran[row * 2] + 1;
    int e0 = tran[row * 2 + 1] + 1;
    for (int d = threadIdx.x; d < Dn; d += 256) {
        float acc = 0.0f;
        for (int s = s0; s < e0; ++s)
            acc += se[((size_t)b * Sn + s) * Dn + d];
        g_t[(size_t)row * Dn + permc(d)] = f2tf(acc);
    }
}

__global__ void tmax_kernel(const float* __restrict__ se, const int* __restrict__ tspan) {
    int b = blockIdx.x;
    int l = tspan[b * 2];
    int r = tspan[b * 2 + 1];
    for (int d = threadIdx.x; d < Dn; d += 256) {
        float m = -3.402823466e38f;
        for (int s = l; s < r; ++s)
            m = fmaxf(m, se[((size_t)b * Sn + s) * Dn + d]);
        g_tmax[(size_t)b * Dn + d] = m;
    }
}

// transpose + round + K-permute 4 weight matrices [K=768, N=768] -> g_Wt[w][N][Kperm]
__global__ void wtrans_kernel(const float* __restrict__ W0, const float* __restrict__ W1,
                              const float* __restrict__ W2, const float* __restrict__ W3) {
    __shared__ float t[32][33];
    int w = blockIdx.z;
    const float* W = (w == 0) ? W0 : (w == 1) ? W1 : (w == 2) ? W2 : W3;
    float* O = g_Wt + (size_t)w * Dn * Dn;
    int nx = blockIdx.x * 32;
    int ky = blockIdx.y * 32;
    int tx = threadIdx.x;
    for (int i = threadIdx.y; i < 32; i += 8)
        t[i][tx] = W[(size_t)(ky + i) * Dn + nx + tx];
    __syncthreads();
    for (int i = threadIdx.y; i < 32; i += 8)
        O[(size_t)(nx + i) * Dn + permc(ky + tx)] = f2tf(t[tx][i]);
}

// ===========================================================================
// tf32 mma.sync GEMM: C[M,N] = A[M,K] @ B^T  (B as [N,K]; K pre-permuted, tf32)
// 128(M) x 96(N) block tile, BK=16, 256 threads (8 warps of 32x48, 4x2 layout)
// 4-stage cp.async pipeline (TSTRIDE=16 conflict-free), 2 CTAs/SM
// Grid tiles chosen for ~86% wave utilization (512 tiles / 296 slots).
// MODE 0: g_x = relu(acc) (exact) + g_xr rounded/permuted    (proj)
// MODE 1: C^T per-batch store into g_tT (rounded/permuted)   (h@W)
// MODE 2: g_x += relu(acc/denom + bias); g_xr copy if WXR    (adjacency)
// ===========================================================================
#define BK 16
#define TSTRIDE 16
#define BN 96
#define TILE_A_F (128 * TSTRIDE)          // 2048 floats
#define TILE_B_F (BN * TSTRIDE)           // 1536 floats
#define STAGE_F (TILE_A_F + TILE_B_F)     // 3584 floats
#define NST 4
#define GEMM_SMEM_BYTES (NST * STAGE_F * 4)   // 57344

template <int MODE, int KTILES, int WXR>
__global__ void __launch_bounds__(256, 2)
gemm_mma(const float* __restrict__ A, const float* __restrict__ B,
         const float* __restrict__ bias, int lda, int ldb) {
    extern __shared__ float smem[];

    int tid = threadIdx.x;
    int lane = tid & 31;
    int warp = tid >> 5;
    int wm = (warp >> 1) * 32;    // warp row base (0/32/64/96)
    int wn = (warp & 1) * 48;     // warp col base (0/48)
    int lg = lane >> 2;           // 0..7
    int tg = lane & 3;            // 0..3

    const float* Ab;
    const float* Bb;
    int aRow0, bRow0;
    if (MODE == 2) {
        Ab = A + (size_t)blockIdx.y * Nn * Nn;     // adj[b]
        Bb = B + (size_t)blockIdx.y * Dn * Nn;     // g_tT[b]
        aRow0 = 0;
        bRow0 = blockIdx.x * BN;
    } else {
        Ab = A;
        Bb = B;
        aRow0 = blockIdx.y * 128;
        bRow0 = blockIdx.x * BN;
    }

    float c[2][6][4];
    #pragma unroll
    for (int i = 0; i < 2; ++i)
        #pragma unroll
        for (int j = 0; j < 6; ++j)
            #pragma unroll
            for (int k = 0; k < 4; ++k) c[i][j][k] = 0.0f;

    uint32_t sAbase[NST], sBbase[NST];
    #pragma unroll
    for (int s = 0; s < NST; ++s) {
        sAbase[s] = smem_u32(smem + s * STAGE_F);
        sBbase[s] = smem_u32(smem + s * STAGE_F + TILE_A_F);
    }

    auto load_stage = [&](int it, int buf) {
        int k0 = it * BK;
        // A: 512 chunks of 16B
        #pragma unroll
        for (int i = 0; i < 2; ++i) {
            int id = tid + i * 256;
            int row = id >> 2;
            int seg = id & 3;
            CP_ASYNC16(sAbase[buf] + (row * TSTRIDE + seg * 4) * 4,
                       Ab + (size_t)(aRow0 + row) * lda + k0 + seg * 4);
        }
        // B: 384 chunks of 16B
        {
            int row = tid >> 2;
            int seg = tid & 3;
            CP_ASYNC16(sBbase[buf] + (row * TSTRIDE + seg * 4) * 4,
                       Bb + (size_t)(bRow0 + row) * ldb + k0 + seg * 4);
            if (tid < 128) {
                int id2 = tid + 256;
                int row2 = id2 >> 2;
                int seg2 = id2 & 3;
                CP_ASYNC16(sBbase[buf] + (row2 * TSTRIDE + seg2 * 4) * 4,
                           Bb + (size_t)(bRow0 + row2) * ldb + k0 + seg2 * 4);
            }
        }
        CP_COMMIT();
    };

    load_stage(0, 0);
    load_stage(1, 1);
    load_stage(2, 2);
    for (int it = 0; it < KTILES; ++it) {
        int buf = it & (NST - 1);
        if (it == KTILES - 1) { CP_WAIT(0); } else { CP_WAIT(2); }
        __syncthreads();
        if (it + 3 < KTILES) load_stage(it + 3, (it + 3) & (NST - 1));

        const float* as = smem + buf * STAGE_F;
        const float* bs = smem + buf * STAGE_F + TILE_A_F;
        // physical cols [4tg..4tg+3] hold logical k = {tg, tg+4, tg+8, tg+12}
        float4 av[2][2], bv[6];
        #pragma unroll
        for (int mi = 0; mi < 2; ++mi) {
            av[mi][0] = *(const float4*)&as[(wm + mi * 16 + lg) * TSTRIDE + 4 * tg];
            av[mi][1] = *(const float4*)&as[(wm + mi * 16 + lg + 8) * TSTRIDE + 4 * tg];
        }
        #pragma unroll
        for (int ni = 0; ni < 6; ++ni)
            bv[ni] = *(const float4*)&bs[(wn + ni * 8 + lg) * TSTRIDE + 4 * tg];
        #pragma unroll
        for (int mi = 0; mi < 2; ++mi)
            #pragma unroll
            for (int ni = 0; ni < 6; ++ni) {
                mma_tf32(c[mi][ni][0], c[mi][ni][1], c[mi][ni][2], c[mi][ni][3],
                         av[mi][0].x, av[mi][1].x, av[mi][0].y, av[mi][1].y,
                         bv[ni].x, bv[ni].y);
                mma_tf32(c[mi][ni][0], c[mi][ni][1], c[mi][ni][2], c[mi][ni][3],
                         av[mi][0].z, av[mi][1].z, av[mi][0].w, av[mi][1].w,
                         bv[ni].z, bv[ni].w);
            }
    }
    __syncthreads();

    // ---- epilogue ----
    if (MODE == 0) {
        size_t row0 = (size_t)blockIdx.y * 128;
        #pragma unroll
        for (int mi = 0; mi < 2; ++mi) {
            int r = wm + mi * 16 + lg;
            #pragma unroll
            for (int ni = 0; ni < 6; ++ni) {
                int cc = blockIdx.x * BN + wn + ni * 8 + 2 * tg;
                float v0 = fmaxf(c[mi][ni][0], 0.0f);
                float v1 = fmaxf(c[mi][ni][1], 0.0f);
                float v2 = fmaxf(c[mi][ni][2], 0.0f);
                float v3 = fmaxf(c[mi][ni][3], 0.0f);
                g_x[(row0 + r) * Dn + cc]          = v0;
                g_x[(row0 + r) * Dn + cc + 1]      = v1;
                g_x[(row0 + r + 8) * Dn + cc]      = v2;
                g_x[(row0 + r + 8) * Dn + cc + 1]  = v3;
                g_xr[(row0 + r) * Dn + permc(cc)]         = f2tf(v0);
                g_xr[(row0 + r) * Dn + permc(cc + 1)]     = f2tf(v1);
                g_xr[(row0 + r + 8) * Dn + permc(cc)]     = f2tf(v2);
                g_xr[(row0 + r + 8) * Dn + permc(cc + 1)] = f2tf(v3);
            }
        }
    } else if (MODE == 1) {
        // stage full 96-col tile transposed: smem[cl*132 + r], cl<96, r<128
        int b = blockIdx.y;
        float* outb = g_tT + ((size_t)b * Dn + blockIdx.x * BN) * Nn;
        #pragma unroll
        for (int mi = 0; mi < 2; ++mi) {
            int r = wm + mi * 16 + lg;
            #pragma unroll
            for (int ni = 0; ni < 6; ++ni) {
                int cl = wn + ni * 8 + 2 * tg;
                smem[cl * 132 + r]           = c[mi][ni][0];
                smem[(cl + 1) * 132 + r]     = c[mi][ni][1];
                smem[cl * 132 + r + 8]       = c[mi][ni][2];
                smem[(cl + 1) * 132 + r + 8] = c[mi][ni][3];
            }
        }
        __syncthreads();
        // write 96 tT rows (each 128 floats) coalesced; permute K(=node) cols
        for (int i = tid; i < BN * 32; i += 256) {
            int row = i >> 5;
            int seg = i & 31;
            float4 v;
            v.x = f2tf(smem[row * 132 + permc(seg * 4 + 0)]);
            v.y = f2tf(smem[row * 132 + permc(seg * 4 + 1)]);
            v.z = f2tf(smem[row * 132 + permc(seg * 4 + 2)]);
            v.w = f2tf(smem[row * 132 + permc(seg * 4 + 3)]);
            *(float4*)&outb[(size_t)row * Nn + seg * 4] = v;
        }
    } else {
        int b = blockIdx.y;
        #pragma unroll
        for (int mi = 0; mi < 2; ++mi) {
            int r = wm + mi * 16 + lg;
            float id0 = 1.0f / g_denom[b * Nn + r];
            float id1 = 1.0f / g_denom[b * Nn + r + 8];
            size_t row0 = (size_t)(b * Nn + r);
            size_t row1 = row0 + 8;
            #pragma unroll
            for (int ni = 0; ni < 6; ++ni) {
                int cc = blockIdx.x * BN + wn + ni * 8 + 2 * tg;
                float n0 = g_x[row0 * Dn + cc]     + fmaxf(c[mi][ni][0] * id0 + bias[cc], 0.0f);
                float n1 = g_x[row0 * Dn + cc + 1] + fmaxf(c[mi][ni][1] * id0 + bias[cc + 1], 0.0f);
                float n2 = g_x[row1 * Dn + cc]     + fmaxf(c[mi][ni][2] * id1 + bias[cc], 0.0f);
                float n3 = g_x[row1 * Dn + cc + 1] + fmaxf(c[mi][ni][3] * id1 + bias[cc + 1], 0.0f);
                g_x[row0 * Dn + cc]     = n0;
                g_x[row0 * Dn + cc + 1] = n1;
                g_x[row1 * Dn + cc]     = n2;
                g_x[row1 * Dn + cc + 1] = n3;
                if (WXR) {
                    g_xr[row0 * Dn + permc(cc)]     = f2tf(n0);
                    g_xr[row0 * Dn + permc(cc + 1)] = f2tf(n1);
                    g_xr[row1 * Dn + permc(cc)]     = f2tf(n2);
                    g_xr[row1 * Dn + permc(cc + 1)] = f2tf(n3);
                }
            }
        }
    }
}

// ===========================================================================
// head: gcn_target (node-span sum) + concat + fc + tanh
// ===========================================================================
__global__ void head_kernel(const float* __restrict__ fcW, const float* __restrict__ fcb,
                            const int* __restrict__ gspan, float* __restrict__ out) {
    int b = blockIdx.x;
    int tid = threadIdx.x;
    int gs = gspan[b * 2];
    int ge = gspan[b * 2 + 1];
    float p0 = 0.0f, p1 = 0.0f, p2 = 0.0f;
    for (int d = tid; d < Dn; d += 256) {
        float tm = g_tmax[(size_t)b * Dn + d];
        float gt = 0.0f;
        for (int n = gs; n < ge; ++n)
            gt += g_x[((size_t)b * Nn + n) * Dn + d];
        p0 += tm * fcW[d * On + 0] + gt * fcW[(Dn + d) * On + 0];
        p1 += tm * fcW[d * On + 1] + gt * fcW[(Dn + d) * On + 1];
        p2 += tm * fcW[d * On + 2] + gt * fcW[(Dn + d) * On + 2];
    }
    __shared__ float r0[256], r1[256], r2[256];
    r0[tid] = p0; r1[tid] = p1; r2[tid] = p2;
    __syncthreads();
    #pragma unroll
    for (int st = 128; st > 0; st >>= 1) {
        if (tid < st) { r0[tid] += r0[tid + st]; r1[tid] += r1[tid + st]; r2[tid] += r2[tid + st]; }
        __syncthreads();
    }
    if (tid == 0) {
        out[b * On + 0] = tanhf(r0[0] + fcb[0]);
        out[b * On + 1] = tanhf(r1[0] + fcb[1]);
        out[b * On + 2] = tanhf(r2[0] + fcb[2]);
    }
}

// ===========================================================================
extern "C" void kernel_launch(void* const* d_in, const int* in_sizes, int n_in,
                              void* d_out, int out_size) {
    const float* se    = (const float*)d_in[0];
    const float* dg    = (const float*)d_in[1];
    const float* dg1   = (const float*)d_in[2];
    const float* Wproj = (const float*)d_in[3];
    const float* Wg1   = (const float*)d_in[4];
    const float* bg1   = (const float*)d_in[5];
    const float* Wg2   = (const float*)d_in[6];
    const float* bg2   = (const float*)d_in[7];
    const float* Wg3   = (const float*)d_in[8];
    const float* bg3   = (const float*)d_in[9];
    const float* fcW   = (const float*)d_in[10];
    const float* fcb   = (const float*)d_in[11];
    const int*   tspan = (const int*)d_in[12];
    const int*   tran  = (const int*)d_in[13];
    const int*   gspan = (const int*)d_in[14];
    float* out = (float*)d_out;

    float *pt, *pxr, *ptT, *padj, *pWt;
    cudaGetSymbolAddress((void**)&pt, g_t);
    cudaGetSymbolAddress((void**)&pxr, g_xr);
    cudaGetSymbolAddress((void**)&ptT, g_tT);
    cudaGetSymbolAddress((void**)&padj, g_adj);
    cudaGetSymbolAddress((void**)&pWt, g_Wt);

    cudaFuncSetAttribute(gemm_mma<0, 48, 1>, cudaFuncAttributeMaxDynamicSharedMemorySize, GEMM_SMEM_BYTES);
    cudaFuncSetAttribute(gemm_mma<1, 48, 0>, cudaFuncAttributeMaxDynamicSharedMemorySize, GEMM_SMEM_BYTES);
    cudaFuncSetAttribute(gemm_mma<2, 8, 1>,  cudaFuncAttributeMaxDynamicSharedMemorySize, GEMM_SMEM_BYTES);
    cudaFuncSetAttribute(gemm_mma<2, 8, 0>,  cudaFuncAttributeMaxDynamicSharedMemorySize, GEMM_SMEM_BYTES);

    dim3 gg(Dn / BN, 64);   // (8, 64) = 512 tiles

    adj_kernel<<<Bn * Nn, 128>>>(dg, dg1);
    span_kernel<<<Bn * Nn, 256>>>(se, tran);
    tmax_kernel<<<Bn, 256>>>(se, tspan);
    wtrans_kernel<<<dim3(24, 24, 4), dim3(32, 8)>>>(Wproj, Wg1, Wg2, Wg3);

    const size_t WSZ = (size_t)Dn * Dn;

    // x = relu(tmps @ W_proj)
    gemm_mma<0, 48, 1><<<gg, 256, GEMM_SMEM_BYTES>>>(pt, pWt + 0 * WSZ, nullptr, Dn, Dn);

    // 3 GCN layers: tT = (x @ Wg)^T ; x += relu(adj @ t / denom + b)
    gemm_mma<1, 48, 0><<<gg, 256, GEMM_SMEM_BYTES>>>(pxr, pWt + 1 * WSZ, nullptr, Dn, Dn);
    gemm_mma<2, 8, 1><<<gg, 256, GEMM_SMEM_BYTES>>>(padj, ptT, bg1, Nn, Nn);
    gemm_mma<1, 48, 0><<<gg, 256, GEMM_SMEM_BYTES>>>(pxr, pWt + 2 * WSZ, nullptr, Dn, Dn);
    gemm_mma<2, 8, 1><<<gg, 256, GEMM_SMEM_BYTES>>>(padj, ptT, bg2, Nn, Nn);
    gemm_mma<1, 48, 0><<<gg, 256, GEMM_SMEM_BYTES>>>(pxr, pWt + 3 * WSZ, nullptr, Dn, Dn);
    gemm_mma<2, 8, 0><<<gg, 256, GEMM_SMEM_BYTES>>>(padj, ptT, bg3, Nn, Nn);

    head_kernel<<<Bn, 256>>>(fcW, fcb, gspan, out);
}

// round 12
// speedup vs baseline: 1.1875x; 1.0039x over previous
#include <cuda_runtime.h>
#include <cstdint>

// Problem constants
#define Bn 64
#define Sn 512
#define Nn 128
#define Dn 768
#define On 3

// Scratch (device globals -- no allocations allowed)
__device__ float g_x[(size_t)Bn * Nn * Dn];      // exact node features (ping)
__device__ float g_x2[(size_t)Bn * Nn * Dn];     // exact node features (pong)
__device__ float g_xr[(size_t)Bn * Nn * Dn];     // tf32-rounded, K-permuted (ping)
__device__ float g_xr2[(size_t)Bn * Nn * Dn];    // tf32-rounded, K-permuted (pong)
__device__ float g_t[(size_t)Bn * Nn * Dn];      // span sums, rounded+permuted [B*N, D]
__device__ float g_adj[(size_t)Bn * Nn * Nn];    // clamped adjacency, permuted cols (exact 0/1)
__device__ float g_denom[(size_t)Bn * Nn];       // row-degree + 1e-7
__device__ float g_tmax[(size_t)Bn * Dn];        // target max-pool
__device__ float g_Wt[4 * (size_t)Dn * Dn];      // W^T [N,K], rounded + K-permuted

// ===========================================================================
// helpers
// ===========================================================================
__device__ __forceinline__ uint32_t smem_u32(const void* p) {
    uint32_t a;
    asm("{ .reg .u64 t; cvta.to.shared.u64 t, %1; cvt.u32.u64 %0, t; }" : "=r"(a) : "l"(p));
    return a;
}
__device__ __forceinline__ float f2tf(float f) {
    uint32_t u;
    asm("cvt.rna.tf32.f32 %0, %1;" : "=r"(u) : "f"(f));
    return __uint_as_float(u);
}
// K-permutation within each 16-column group (involution)
__device__ __forceinline__ int permc(int c) {
    return (c & ~15) | ((c & 3) << 2) | ((c >> 2) & 3);
}
#define CP_ASYNC16(dst, src) \
    asm volatile("cp.async.cg.shared.global [%0], [%1], 16;" :: "r"(dst), "l"(src) : "memory")
#define CP_COMMIT() asm volatile("cp.async.commit_group;" ::: "memory")
#define CP_WAIT(n)  asm volatile("cp.async.wait_group %0;" :: "n"(n) : "memory")

__device__ __forceinline__ void mma_tf32(float& c0, float& c1, float& c2, float& c3,
                                         float a0, float a1, float a2, float a3,
                                         float b0, float b1) {
    asm volatile(
        "mma.sync.aligned.m16n8k8.row.col.f32.tf32.tf32.f32 "
        "{%0,%1,%2,%3}, {%4,%5,%6,%7}, {%8,%9}, {%0,%1,%2,%3};"
        : "+f"(c0), "+f"(c1), "+f"(c2), "+f"(c3)
        : "r"(__float_as_uint(a0)), "r"(__float_as_uint(a1)),
          "r"(__float_as_uint(a2)), "r"(__float_as_uint(a3)),
          "r"(__float_as_uint(b0)), "r"(__float_as_uint(b1)));
}

// ===========================================================================
// small prep kernels
// ===========================================================================
__global__ void adj_kernel(const float* __restrict__ dg, const float* __restrict__ dg1) {
    int row = blockIdx.x;
    int tid = threadIdx.x;
    float a = dg[(size_t)row * Nn + tid] + dg1[(size_t)row * Nn + tid];
    a = fminf(a, 1.0f);
    g_adj[(size_t)row * Nn + permc(tid)] = a;
    __shared__ float s[128];
    s[tid] = a;
    __syncthreads();
    #pragma unroll
    for (int st = 64; st > 0; st >>= 1) {
        if (tid < st) s[tid] += s[tid + st];
        __syncthreads();
    }
    if (tid == 0) g_denom[row] = s[0] + 1e-7f;
}

__global__ void span_kernel(const float* __restrict__ se, const int* __restrict__ tran) {
    int row = blockIdx.x;
    int b = row >> 7;
    int s0 = tran[row * 2] + 1;
    int e0 = tran[row * 2 + 1] + 1;
    for (int d = threadIdx.x; d < Dn; d += 256) {
        float acc = 0.0f;
        for (int s = s0; s < e0; ++s)
            acc += se[((size_t)b * Sn + s) * Dn + d];
        g_t[(size_t)row * Dn + permc(d)] = f2tf(acc);
    }
}

__global__ void tmax_kernel(const float* __restrict__ se, const int* __restrict__ tspan) {
    int b = blockIdx.x;
    int l = tspan[b * 2];
    int r = tspan[b * 2 + 1];
    for (int d = threadIdx.x; d < Dn; d += 256) {
        float m = -3.402823466e38f;
        for (int s = l; s < r; ++s)
            m = fmaxf(m, se[((size_t)b * Sn + s) * Dn + d]);
        g_tmax[(size_t)b * Dn + d] = m;
    }
}

// transpose + round + K-permute 4 weight matrices [K=768, N=768] -> g_Wt[w][N][Kperm]
__global__ void wtrans_kernel(const float* __restrict__ W0, const float* __restrict__ W1,
                              const float* __restrict__ W2, const float* __restrict__ W3) {
    __shared__ float t[32][33];
    int w = blockIdx.z;
    const float* W = (w == 0) ? W0 : (w == 1) ? W1 : (w == 2) ? W2 : W3;
    float* O = g_Wt + (size_t)w * Dn * Dn;
    int nx = blockIdx.x * 32;
    int ky = blockIdx.y * 32;
    int tx = threadIdx.x;
    for (int i = threadIdx.y; i < 32; i += 8)
        t[i][tx] = W[(size_t)(ky + i) * Dn + nx + tx];
    __syncthreads();
    for (int i = threadIdx.y; i < 32; i += 8)
        O[(size_t)(nx + i) * Dn + permc(ky + tx)] = f2tf(t[tx][i]);
}

// ===========================================================================
// shared tile geometry (128(M) x 96(N), BK=16, 8 warps of 32x48)
// ===========================================================================
#define BK 16
#define TSTRIDE 16
#define BN 96
#define TILE_A_F (128 * TSTRIDE)          // 2048 floats
#define TILE_B_F (BN * TSTRIDE)           // 1536 floats
#define STAGE_F (TILE_A_F + TILE_B_F)     // 3584 floats
#define NST 4
#define REGION0_F (NST * STAGE_F)         // 14336 floats (pipeline / P^T staging)
#define GEMM_SMEM_BYTES (REGION0_F * 4)   // 57344
#define FUSED_SMEM_BYTES ((REGION0_F + NST * TILE_A_F) * 4)  // 90112

// ===========================================================================
// projection GEMM: xo = relu(g_t @ Wproj^T); xro = rounded/permuted copy
// ===========================================================================
template <int KTILES>
__global__ void __launch_bounds__(256, 2)
gemm_proj(const float* __restrict__ A, const float* __restrict__ B,
          float* __restrict__ Xout, float* __restrict__ XRout) {
    extern __shared__ float smem[];
    int tid = threadIdx.x;
    int lane = tid & 31;
    int warp = tid >> 5;
    int wm = (warp >> 1) * 32;
    int wn = (warp & 1) * 48;
    int lg = lane >> 2;
    int tg = lane & 3;

    int aRow0 = blockIdx.y * 128;
    int bRow0 = blockIdx.x * BN;

    float c[2][6][4];
    #pragma unroll
    for (int i = 0; i < 2; ++i)
        #pragma unroll
        for (int j = 0; j < 6; ++j)
            #pragma unroll
            for (int k = 0; k < 4; ++k) c[i][j][k] = 0.0f;

    uint32_t sAbase[NST], sBbase[NST];
    #pragma unroll
    for (int s = 0; s < NST; ++s) {
        sAbase[s] = smem_u32(smem + s * STAGE_F);
        sBbase[s] = smem_u32(smem + s * STAGE_F + TILE_A_F);
    }

    auto load_stage = [&](int it, int buf) {
        int k0 = it * BK;
        #pragma unroll
        for (int i = 0; i < 2; ++i) {
            int id = tid + i * 256;
            int row = id >> 2;
            int seg = id & 3;
            CP_ASYNC16(sAbase[buf] + (row * TSTRIDE + seg * 4) * 4,
                       A + (size_t)(aRow0 + row) * Dn + k0 + seg * 4);
        }
        {
            int row = tid >> 2;
            int seg = tid & 3;
            CP_ASYNC16(sBbase[buf] + (row * TSTRIDE + seg * 4) * 4,
                       B + (size_t)(bRow0 + row) * Dn + k0 + seg * 4);
            if (tid < 128) {
                int id2 = tid + 256;
                int row2 = id2 >> 2;
                int seg2 = id2 & 3;
                CP_ASYNC16(sBbase[buf] + (row2 * TSTRIDE + seg2 * 4) * 4,
                           B + (size_t)(bRow0 + row2) * Dn + k0 + seg2 * 4);
            }
        }
        CP_COMMIT();
    };

    load_stage(0, 0);
    load_stage(1, 1);
    load_stage(2, 2);
    for (int it = 0; it < KTILES; ++it) {
        int buf = it & (NST - 1);
        if (it == KTILES - 1) { CP_WAIT(0); } else { CP_WAIT(2); }
        __syncthreads();
        if (it + 3 < KTILES) load_stage(it + 3, (it + 3) & (NST - 1));

        const float* as = smem + buf * STAGE_F;
        const float* bs = smem + buf * STAGE_F + TILE_A_F;
        float4 av[2][2], bv[6];
        #pragma unroll
        for (int mi = 0; mi < 2; ++mi) {
            av[mi][0] = *(const float4*)&as[(wm + mi * 16 + lg) * TSTRIDE + 4 * tg];
            av[mi][1] = *(const float4*)&as[(wm + mi * 16 + lg + 8) * TSTRIDE + 4 * tg];
        }
        #pragma unroll
        for (int ni = 0; ni < 6; ++ni)
            bv[ni] = *(const float4*)&bs[(wn + ni * 8 + lg) * TSTRIDE + 4 * tg];
        #pragma unroll
        for (int mi = 0; mi < 2; ++mi)
            #pragma unroll
            for (int ni = 0; ni < 6; ++ni) {
                mma_tf32(c[mi][ni][0], c[mi][ni][1], c[mi][ni][2], c[mi][ni][3],
                         av[mi][0].x, av[mi][1].x, av[mi][0].y, av[mi][1].y,
                         bv[ni].x, bv[ni].y);
                mma_tf32(c[mi][ni][0], c[mi][ni][1], c[mi][ni][2], c[mi][ni][3],
                         av[mi][0].z, av[mi][1].z, av[mi][0].w, av[mi][1].w,
                         bv[ni].z, bv[ni].w);
            }
    }

    size_t row0 = (size_t)blockIdx.y * 128;
    #pragma unroll
    for (int mi = 0; mi < 2; ++mi) {
        int r = wm + mi * 16 + lg;
        #pragma unroll
        for (int ni = 0; ni < 6; ++ni) {
            int cc = blockIdx.x * BN + wn + ni * 8 + 2 * tg;
            float v0 = fmaxf(c[mi][ni][0], 0.0f);
            float v1 = fmaxf(c[mi][ni][1], 0.0f);
            float v2 = fmaxf(c[mi][ni][2], 0.0f);
            float v3 = fmaxf(c[mi][ni][3], 0.0f);
            Xout[(row0 + r) * Dn + cc]          = v0;
            Xout[(row0 + r) * Dn + cc + 1]      = v1;
            Xout[(row0 + r + 8) * Dn + cc]      = v2;
            Xout[(row0 + r + 8) * Dn + cc + 1]  = v3;
            XRout[(row0 + r) * Dn + permc(cc)]         = f2tf(v0);
            XRout[(row0 + r) * Dn + permc(cc + 1)]     = f2tf(v1);
            XRout[(row0 + r + 8) * Dn + permc(cc)]     = f2tf(v2);
            XRout[(row0 + r + 8) * Dn + permc(cc + 1)] = f2tf(v3);
        }
    }
}

// ===========================================================================
// FUSED GCN layer (ping-pong, race-free): per (dtile=blockIdx.x, b=blockIdx.y)
//   phase 1: P = XRin[b] @ Wg^T          (48 k-tiles, pipeline in region0)
//   stage:   P^T rounded+permuted into region0 as 8 k-chunked [96][16] tiles
//   phase 2: acc = adj[b] @ P            (8 k-tiles, adj pipeline in region1)
//   epilogue: Xout = Xin + relu(acc/denom + bias); XRout rounded if WXR
//   Inputs (XRin, Xin) are NEVER written by this kernel -> no cross-CTA race.
// ===========================================================================
template <int WXR>
__global__ void __launch_bounds__(256, 2)
gcn_fused(const float* __restrict__ XRin, const float* __restrict__ Xin,
          float* __restrict__ Xout, float* __restrict__ XRout,
          const float* __restrict__ B, const float* __restrict__ bias) {
    extern __shared__ float smem[];
    int tid = threadIdx.x;
    int lane = tid & 31;
    int warp = tid >> 5;
    int wm = (warp >> 1) * 32;
    int wn = (warp & 1) * 48;
    int lg = lane >> 2;
    int tg = lane & 3;

    int b = blockIdx.y;
    int aRow0 = b * 128;
    int bRow0 = blockIdx.x * BN;

    float c[2][6][4];
    #pragma unroll
    for (int i = 0; i < 2; ++i)
        #pragma unroll
        for (int j = 0; j < 6; ++j)
            #pragma unroll
            for (int k = 0; k < 4; ++k) c[i][j][k] = 0.0f;

    uint32_t sAbase[NST], sBbase[NST], sAdj[NST];
    #pragma unroll
    for (int s = 0; s < NST; ++s) {
        sAbase[s] = smem_u32(smem + s * STAGE_F);
        sBbase[s] = smem_u32(smem + s * STAGE_F + TILE_A_F);
        sAdj[s]   = smem_u32(smem + REGION0_F + s * TILE_A_F);
    }

    // ---- phase 1: P = XRin[b] @ W^T ----
    auto load_stage = [&](int it, int buf) {
        int k0 = it * BK;
        #pragma unroll
        for (int i = 0; i < 2; ++i) {
            int id = tid + i * 256;
            int row = id >> 2;
            int seg = id & 3;
            CP_ASYNC16(sAbase[buf] + (row * TSTRIDE + seg * 4) * 4,
                       XRin + (size_t)(aRow0 + row) * Dn + k0 + seg * 4);
        }
        {
            int row = tid >> 2;
            int seg = tid & 3;
            CP_ASYNC16(sBbase[buf] + (row * TSTRIDE + seg * 4) * 4,
                       B + (size_t)(bRow0 + row) * Dn + k0 + seg * 4);
            if (tid < 128) {
                int id2 = tid + 256;
                int row2 = id2 >> 2;
                int seg2 = id2 & 3;
                CP_ASYNC16(sBbase[buf] + (row2 * TSTRIDE + seg2 * 4) * 4,
                           B + (size_t)(bRow0 + row2) * Dn + k0 + seg2 * 4);
            }
        }
        CP_COMMIT();
    };

    load_stage(0, 0);
    load_stage(1, 1);
    load_stage(2, 2);
    const int KT1 = Dn / BK;   // 48
    for (int it = 0; it < KT1; ++it) {
        int buf = it & (NST - 1);
        if (it == KT1 - 1) { CP_WAIT(0); } else { CP_WAIT(2); }
        __syncthreads();
        if (it + 3 < KT1) load_stage(it + 3, (it + 3) & (NST - 1));

        const float* as = smem + buf * STAGE_F;
        const float* bs = smem + buf * STAGE_F + TILE_A_F;
        float4 av[2][2], bv[6];
        #pragma unroll
        for (int mi = 0; mi < 2; ++mi) {
            av[mi][0] = *(const float4*)&as[(wm + mi * 16 + lg) * TSTRIDE + 4 * tg];
            av[mi][1] = *(const float4*)&as[(wm + mi * 16 + lg + 8) * TSTRIDE + 4 * tg];
        }
        #pragma unroll
        for (int ni = 0; ni < 6; ++ni)
            bv[ni] = *(const float4*)&bs[(wn + ni * 8 + lg) * TSTRIDE + 4 * tg];
        #pragma unroll
        for (int mi = 0; mi < 2; ++mi)
            #pragma unroll
            for (int ni = 0; ni < 6; ++ni) {
                mma_tf32(c[mi][ni][0], c[mi][ni][1], c[mi][ni][2], c[mi][ni][3],
                         av[mi][0].x, av[mi][1].x, av[mi][0].y, av[mi][1].y,
                         bv[ni].x, bv[ni].y);
                mma_tf32(c[mi][ni][0], c[mi][ni][1], c[mi][ni][2], c[mi][ni][3],
                         av[mi][0].z, av[mi][1].z, av[mi][0].w, av[mi][1].w,
                         bv[ni].z, bv[ni].w);
            }
    }
    __syncthreads();

    // ---- stage P^T into region0: 8 k-chunked tiles [96 d-rows][16 node-cols] ----
    // P[m][d] -> smem[(m>>4)*TILE_B_F + d*16 + (permc(m)&15)], rounded to tf32
    #pragma unroll
    for (int mi = 0; mi < 2; ++mi) {
        int r0i = wm + mi * 16 + lg;
        int r1i = r0i + 8;
        int t0 = (r0i >> 4) * TILE_B_F + (permc(r0i) & 15);
        int t1 = (r1i >> 4) * TILE_B_F + (permc(r1i) & 15);
        #pragma unroll
        for (int ni = 0; ni < 6; ++ni) {
            int cl = wn + ni * 8 + 2 * tg;
            smem[t0 + cl * 16]        = f2tf(c[mi][ni][0]);
            smem[t0 + (cl + 1) * 16]  = f2tf(c[mi][ni][1]);
            smem[t1 + cl * 16]        = f2tf(c[mi][ni][2]);
            smem[t1 + (cl + 1) * 16]  = f2tf(c[mi][ni][3]);
            c[mi][ni][0] = 0.0f; c[mi][ni][1] = 0.0f;
            c[mi][ni][2] = 0.0f; c[mi][ni][3] = 0.0f;
        }
    }
    __syncthreads();

    // ---- phase 2: acc = adj[b] @ P  (K = 128 nodes, 8 k-tiles) ----
    const float* adjb = g_adj + (size_t)b * Nn * Nn;
    auto load_adj = [&](int it, int buf) {
        int k0 = it * BK;
        #pragma unroll
        for (int i = 0; i < 2; ++i) {
            int id = tid + i * 256;
            int row = id >> 2;
            int seg = id & 3;
            CP_ASYNC16(sAdj[buf] + (row * TSTRIDE + seg * 4) * 4,
                       adjb + (size_t)row * Nn + k0 + seg * 4);
        }
        CP_COMMIT();
    };

    load_adj(0, 0);
    load_adj(1, 1);
    load_adj(2, 2);
    for (int it = 0; it < 8; ++it) {
        int buf = it & (NST - 1);
        if (it == 7) { CP_WAIT(0); } else { CP_WAIT(2); }
        __syncthreads();
        if (it + 3 < 8) load_adj(it + 3, (it + 3) & (NST - 1));

        const float* as = smem + REGION0_F + buf * TILE_A_F;
        const float* bs = smem + it * TILE_B_F;
        float4 av[2][2], bv[6];
        #pragma unroll
        for (int mi = 0; mi < 2; ++mi) {
            av[mi][0] = *(const float4*)&as[(wm + mi * 16 + lg) * TSTRIDE + 4 * tg];
            av[mi][1] = *(const float4*)&as[(wm + mi * 16 + lg + 8) * TSTRIDE + 4 * tg];
        }
        #pragma unroll
        for (int ni = 0; ni < 6; ++ni)
            bv[ni] = *(const float4*)&bs[(wn + ni * 8 + lg) * TSTRIDE + 4 * tg];
        #pragma unroll
        for (int mi = 0; mi < 2; ++mi)
            #pragma unroll
            for (int ni = 0; ni < 6; ++ni) {
                mma_tf32(c[mi][ni][0], c[mi][ni][1], c[mi][ni][2], c[mi][ni][3],
                         av[mi][0].x, av[mi][1].x, av[mi][0].y, av[mi][1].y,
                         bv[ni].x, bv[ni].y);
                mma_tf32(c[mi][ni][0], c[mi][ni][1], c[mi][ni][2], c[mi][ni][3],
                         av[mi][0].z, av[mi][1].z, av[mi][0].w, av[mi][1].w,
                         bv[ni].z, bv[ni].w);
            }
    }

    // ---- epilogue: residual + relu + bias (reads Xin, writes Xout/XRout) ----
    #pragma unroll
    for (int mi = 0; mi < 2; ++mi) {
        int r = wm + mi * 16 + lg;
        float id0 = 1.0f / g_denom[b * Nn + r];
        float id1 = 1.0f / g_denom[b * Nn + r + 8];
        size_t row0 = (size_t)(b * Nn + r);
        size_t row1 = row0 + 8;
        #pragma unroll
        for (int ni = 0; ni < 6; ++ni) {
            int cc = blockIdx.x * BN + wn + ni * 8 + 2 * tg;
            float n0 = Xin[row0 * Dn + cc]     + fmaxf(c[mi][ni][0] * id0 + bias[cc], 0.0f);
            float n1 = Xin[row0 * Dn + cc + 1] + fmaxf(c[mi][ni][1] * id0 + bias[cc + 1], 0.0f);
            float n2 = Xin[row1 * Dn + cc]     + fmaxf(c[mi][ni][2] * id1 + bias[cc], 0.0f);
            float n3 = Xin[row1 * Dn + cc + 1] + fmaxf(c[mi][ni][3] * id1 + bias[cc + 1], 0.0f);
            Xout[row0 * Dn + cc]     = n0;
            Xout[row0 * Dn + cc + 1] = n1;
            Xout[row1 * Dn + cc]     = n2;
            Xout[row1 * Dn + cc + 1] = n3;
            if (WXR) {
                XRout[row0 * Dn + permc(cc)]     = f2tf(n0);
                XRout[row0 * Dn + permc(cc + 1)] = f2tf(n1);
                XRout[row1 * Dn + permc(cc)]     = f2tf(n2);
                XRout[row1 * Dn + permc(cc + 1)] = f2tf(n3);
            }
        }
    }
}

// ===========================================================================
// head: gcn_target (node-span sum) + concat + fc + tanh (reads Xfinal)
// ===========================================================================
__global__ void head_kernel(const float* __restrict__ Xfinal,
                            const float* __restrict__ fcW, const float* __restrict__ fcb,
                            const int* __restrict__ gspan, float* __restrict__ out) {
    int b = blockIdx.x;
    int tid = threadIdx.x;
    int gs = gspan[b * 2];
    int ge = gspan[b * 2 + 1];
    float p0 = 0.0f, p1 = 0.0f, p2 = 0.0f;
    for (int d = tid; d < Dn; d += 256) {
        float tm = g_tmax[(size_t)b * Dn + d];
        float gt = 0.0f;
        for (int n = gs; n < ge; ++n)
            gt += Xfinal[((size_t)b * Nn + n) * Dn + d];
        p0 += tm * fcW[d * On + 0] + gt * fcW[(Dn + d) * On + 0];
        p1 += tm * fcW[d * On + 1] + gt * fcW[(Dn + d) * On + 1];
        p2 += tm * fcW[d * On + 2] + gt * fcW[(Dn + d) * On + 2];
    }
    __shared__ float r0[256], r1[256], r2[256];
    r0[tid] = p0; r1[tid] = p1; r2[tid] = p2;
    __syncthreads();
    #pragma unroll
    for (int st = 128; st > 0; st >>= 1) {
        if (tid < st) { r0[tid] += r0[tid + st]; r1[tid] += r1[tid + st]; r2[tid] += r2[tid + st]; }
        __syncthreads();
    }
    if (tid == 0) {
        out[b * On + 0] = tanhf(r0[0] + fcb[0]);
        out[b * On + 1] = tanhf(r1[0] + fcb[1]);
        out[b * On + 2] = tanhf(r2[0] + fcb[2]);
    }
}

// ===========================================================================
extern "C" void kernel_launch(void* const* d_in, const int* in_sizes, int n_in,
                              void* d_out, int out_size) {
    const float* se    = (const float*)d_in[0];
    const float* dg    = (const float*)d_in[1];
    const float* dg1   = (const float*)d_in[2];
    const float* Wproj = (const float*)d_in[3];
    const float* Wg1   = (const float*)d_in[4];
    const float* bg1   = (const float*)d_in[5];
    const float* Wg2   = (const float*)d_in[6];
    const float* bg2   = (const float*)d_in[7];
    const float* Wg3   = (const float*)d_in[8];
    const float* bg3   = (const float*)d_in[9];
    const float* fcW   = (const float*)d_in[10];
    const float* fcb   = (const float*)d_in[11];
    const int*   tspan = (const int*)d_in[12];
    const int*   tran  = (const int*)d_in[13];
    const int*   gspan = (const int*)d_in[14];
    float* out = (float*)d_out;

    float *pt, *px, *px2, *pxr, *pxr2, *pWt;
    cudaGetSymbolAddress((void**)&pt, g_t);
    cudaGetSymbolAddress((void**)&px, g_x);
    cudaGetSymbolAddress((void**)&px2, g_x2);
    cudaGetSymbolAddress((void**)&pxr, g_xr);
    cudaGetSymbolAddress((void**)&pxr2, g_xr2);
    cudaGetSymbolAddress((void**)&pWt, g_Wt);

    cudaFuncSetAttribute(gemm_proj<48>, cudaFuncAttributeMaxDynamicSharedMemorySize, GEMM_SMEM_BYTES);
    cudaFuncSetAttribute(gcn_fused<1>, cudaFuncAttributeMaxDynamicSharedMemorySize, FUSED_SMEM_BYTES);
    cudaFuncSetAttribute(gcn_fused<0>, cudaFuncAttributeMaxDynamicSharedMemorySize, FUSED_SMEM_BYTES);

    dim3 gg(Dn / BN, 64);   // (8, 64) = 512 tiles

    adj_kernel<<<Bn * Nn, 128>>>(dg, dg1);
    span_kernel<<<Bn * Nn, 256>>>(se, tran);
    tmax_kernel<<<Bn, 256>>>(se, tspan);
    wtrans_kernel<<<dim3(24, 24, 4), dim3(32, 8)>>>(Wproj, Wg1, Wg2, Wg3);

    const size_t WSZ = (size_t)Dn * Dn;

    // x = relu(tmps @ W_proj)  -> (g_x, g_xr)
    gemm_proj<48><<<gg, 256, GEMM_SMEM_BYTES>>>(pt, pWt + 0 * WSZ, px, pxr);

    // 3 fused GCN layers, ping-pong buffers (inputs never written in-kernel)
    gcn_fused<1><<<gg, 256, FUSED_SMEM_BYTES>>>(pxr,  px,  px2, pxr2, pWt + 1 * WSZ, bg1);
    gcn_fused<1><<<gg, 256, FUSED_SMEM_BYTES>>>(pxr2, px2, px,  pxr,  pWt + 2 * WSZ, bg2);
    gcn_fused<0><<<gg, 256, FUSED_SMEM_BYTES>>>(pxr,  px,  px2, nullptr, pWt + 3 * WSZ, bg3);

    head_kernel<<<Bn, 256>>>(px2, fcW, fcb, gspan, out);
}